// round 3
// baseline (speedup 1.0000x reference)
#include <cuda_runtime.h>
#include <cuda_bf16.h>

// ---------------------------------------------------------------------------
// BSAM: self-attention block
//   Q = conv3x3(A1_B, w1,b1)  -> [b, n, 32]
//   K = conv3x3(A1_C, w2,b2)  -> [b, 32, n]   (stored transposed: [b, n, 32])
//   V = conv3x3(A1_C, w3,b3)  -> [b, n, 64]
//   O = softmax(Q K) V ; out = O^T reshaped + A1_C
// B=4, C=64, H=W=64, n=4096
// ---------------------------------------------------------------------------

#define NB   4
#define NC   64
#define HW   64
#define NPIX 4096      // HW*HW
#define CH   32        // C/2

// scratch (device globals; allocation-free per harness rules)
__device__ __align__(16) float g_Q[NB * NPIX * CH];    // [b][p][c]   2 MB
__device__ __align__(16) float g_K[NB * NPIX * CH];    // [b][p][c]   2 MB (K^T)
__device__ __align__(16) float g_V[NB * NPIX * NC];    // [b][p][c]   4 MB
__device__ __align__(16) float g_wpack[64 * 9 * 128];  // [ci][dy][dx][co] 294 KB
__device__ __align__(16) float g_bias[128];

// ---------------------------------------------------------------------------
// Weight repack: co-contiguous so the conv inner loop does uniform LDG.128
// co 0..31 = w1 (Q), 32..63 = w2 (K), 64..127 = w3 (V)
// ---------------------------------------------------------------------------
__global__ void pack_kernel(const float* __restrict__ w1, const float* __restrict__ b1,
                            const float* __restrict__ w2, const float* __restrict__ b2,
                            const float* __restrict__ w3, const float* __restrict__ b3) {
    int idx = blockIdx.x * 256 + threadIdx.x;
    if (idx < 128) {
        g_bias[idx] = (idx < 32) ? b1[idx] : (idx < 64) ? b2[idx - 32] : b3[idx - 64];
    }
    if (idx < 64 * 9 * 128) {
        int co = idx & 127;
        int t  = idx >> 7;          // (ci*3+dy)*3+dx
        int ci = t / 9;
        int k  = t % 9;
        float v;
        if (co < 32)       v = w1[(co * 64 + ci) * 9 + k];
        else if (co < 64)  v = w2[((co - 32) * 64 + ci) * 9 + k];
        else               v = w3[((co - 64) * 64 + ci) * 9 + k];
        g_wpack[idx] = v;
    }
}

// ---------------------------------------------------------------------------
// Conv: block = (row y, batch b). SMEM holds 3 input rows x 64 ch for BOTH
// inputs (x-padded to 66). Thread = (x, group g). Group g owns output
// channels [32g, 32g+32): g=0 -> Q (input B), g=1 -> K (input C), g=2,3 -> V.
// 16 accumulators per pass, weights via uniform float4 loads.
// ---------------------------------------------------------------------------
#define CONV_SMEM (2 * 64 * 3 * 66 * 4)

__global__ __launch_bounds__(256)
void conv_kernel(const float* __restrict__ A1B, const float* __restrict__ A1C) {
    extern __shared__ float smem[];
    float* sB = smem;                  // [64][3][66]
    float* sC = smem + 64 * 3 * 66;

    const int y   = blockIdx.x;
    const int b   = blockIdx.y;
    const int tid = threadIdx.x;

    for (int idx = tid; idx < 64 * 3 * 66; idx += 256) {
        int ci  = idx / 198;
        int rem = idx % 198;
        int r   = rem / 66;
        int xx  = rem % 66;
        int yy  = y + r - 1;
        int x   = xx - 1;
        bool ok = (yy >= 0) && (yy < HW) && (x >= 0) && (x < HW);
        float vb = 0.f, vc = 0.f;
        if (ok) {
            int gi = ((b * 64 + ci) * HW + yy) * HW + x;
            vb = __ldg(A1B + gi);
            vc = __ldg(A1C + gi);
        }
        sB[idx] = vb;
        sC[idx] = vc;
    }
    __syncthreads();

    const int x = tid & 63;
    const int g = tid >> 6;
    const float* sIn = (g == 0) ? sB : sC;
    const int p = y * HW + x;

    #pragma unroll
    for (int pass = 0; pass < 2; ++pass) {
        const int co0 = g * 32 + pass * 16;
        float acc[16];
        #pragma unroll
        for (int u = 0; u < 16; ++u) acc[u] = g_bias[co0 + u];

        for (int ci = 0; ci < 64; ++ci) {
            #pragma unroll
            for (int dy = 0; dy < 3; ++dy) {
                const float* row = sIn + (ci * 3 + dy) * 66 + x; // row[0]=x-1
                float in0 = row[0], in1 = row[1], in2 = row[2];
                #pragma unroll
                for (int dx = 0; dx < 3; ++dx) {
                    float iv = (dx == 0) ? in0 : (dx == 1) ? in1 : in2;
                    const float4* wr = reinterpret_cast<const float4*>(
                        g_wpack + ((ci * 3 + dy) * 3 + dx) * 128 + co0);
                    float4 wa = __ldg(wr + 0);
                    float4 wb = __ldg(wr + 1);
                    float4 wc = __ldg(wr + 2);
                    float4 wd = __ldg(wr + 3);
                    acc[0]  += wa.x * iv;  acc[1]  += wa.y * iv;
                    acc[2]  += wa.z * iv;  acc[3]  += wa.w * iv;
                    acc[4]  += wb.x * iv;  acc[5]  += wb.y * iv;
                    acc[6]  += wb.z * iv;  acc[7]  += wb.w * iv;
                    acc[8]  += wc.x * iv;  acc[9]  += wc.y * iv;
                    acc[10] += wc.z * iv;  acc[11] += wc.w * iv;
                    acc[12] += wd.x * iv;  acc[13] += wd.y * iv;
                    acc[14] += wd.z * iv;  acc[15] += wd.w * iv;
                }
            }
        }

        float* dst;
        if (g == 0)      dst = g_Q + (b * NPIX + p) * CH + co0;
        else if (g == 1) dst = g_K + (b * NPIX + p) * CH + (co0 - 32);
        else             dst = g_V + (b * NPIX + p) * NC + (co0 - 64);
        #pragma unroll
        for (int u = 0; u < 16; u += 4)
            *reinterpret_cast<float4*>(dst + u) =
                make_float4(acc[u], acc[u + 1], acc[u + 2], acc[u + 3]);
    }
}

// ---------------------------------------------------------------------------
// Fused flash attention (fp32). Block = (query tile rb of 64 rows, batch b).
// 256 threads = 16x16; each thread owns a 4x4 micro-tile of S/P and of O.
// Online softmax; row reductions via half-warp shfl (rows of one ty live in
// one 16-lane group). P staged through padded SMEM for the PV GEMM.
// ---------------------------------------------------------------------------
#define QS_N   (64 * 33)   // pad 33: conflict-free
#define KS_N   (64 * 33)
#define VS_N   (64 * 64)   // float4 rows, 256B aligned
#define PS_N   (64 * 65)   // pad 65: conflict-free broadcast loads
#define ATTN_SMEM ((QS_N + KS_N + VS_N + PS_N) * 4)

__global__ __launch_bounds__(256)
void attn_kernel(const float* __restrict__ A1C, float* __restrict__ out) {
    extern __shared__ float sm[];
    float* Qs = sm;
    float* Ks = Qs + QS_N;
    float* Vs = Ks + KS_N;
    float* Ps = Vs + VS_N;

    const int rb  = blockIdx.x;     // query tile (64 rows)
    const int b   = blockIdx.y;
    const int tid = threadIdx.x;
    const int tx  = tid & 15;       // output/key columns: tx*4 .. +3
    const int ty  = tid >> 4;       // query rows:        ty*4 .. +3

    // load Q tile [64][32] -> padded SMEM
    {
        const float4* qg = reinterpret_cast<const float4*>(g_Q + (b * NPIX + rb * 64) * CH);
        for (int fi = tid; fi < 512; fi += 256) {
            float4 v = __ldg(qg + fi);
            int r = fi >> 3, k4 = fi & 7;
            float* d = Qs + r * 33 + k4 * 4;
            d[0] = v.x; d[1] = v.y; d[2] = v.z; d[3] = v.w;
        }
    }

    float o[4][4] = {};
    float m[4], l[4];
    #pragma unroll
    for (int i = 0; i < 4; ++i) { m[i] = -1e30f; l[i] = 0.f; }

    for (int kb = 0; kb < 64; ++kb) {
        __syncthreads();   // prev PV done reading Ks/Vs/Ps; also covers Q on iter 0
        // load K chunk [64][32] and V chunk [64][64]
        {
            const float4* kg = reinterpret_cast<const float4*>(g_K + (b * NPIX + kb * 64) * CH);
            for (int fi = tid; fi < 512; fi += 256) {
                float4 v = __ldg(kg + fi);
                int r = fi >> 3, k4 = fi & 7;
                float* d = Ks + r * 33 + k4 * 4;
                d[0] = v.x; d[1] = v.y; d[2] = v.z; d[3] = v.w;
            }
            const float4* vg = reinterpret_cast<const float4*>(g_V + (b * NPIX + kb * 64) * NC);
            float4* vs4 = reinterpret_cast<float4*>(Vs);
            for (int fi = tid; fi < 1024; fi += 256) vs4[fi] = __ldg(vg + fi);
        }
        __syncthreads();

        // S = Q K^T  (4x4 per thread, contract over 32)
        float s[4][4] = {};
        #pragma unroll 4
        for (int k = 0; k < 32; ++k) {
            float qv[4], kv[4];
            #pragma unroll
            for (int i = 0; i < 4; ++i) qv[i] = Qs[(ty * 4 + i) * 33 + k];
            #pragma unroll
            for (int j = 0; j < 4; ++j) kv[j] = Ks[(tx * 4 + j) * 33 + k];
            #pragma unroll
            for (int i = 0; i < 4; ++i)
                #pragma unroll
                for (int j = 0; j < 4; ++j) s[i][j] += qv[i] * kv[j];
        }

        // online softmax per row (row group = 16 lanes sharing ty)
        #pragma unroll
        for (int i = 0; i < 4; ++i) {
            float mx = fmaxf(fmaxf(s[i][0], s[i][1]), fmaxf(s[i][2], s[i][3]));
            mx = fmaxf(mx, __shfl_xor_sync(0xffffffffu, mx, 1, 16));
            mx = fmaxf(mx, __shfl_xor_sync(0xffffffffu, mx, 2, 16));
            mx = fmaxf(mx, __shfl_xor_sync(0xffffffffu, mx, 4, 16));
            mx = fmaxf(mx, __shfl_xor_sync(0xffffffffu, mx, 8, 16));
            float mn    = fmaxf(m[i], mx);
            float alpha = __expf(m[i] - mn);
            float sum = 0.f;
            #pragma unroll
            for (int j = 0; j < 4; ++j) {
                float e = __expf(s[i][j] - mn);
                s[i][j] = e;
                sum += e;
            }
            sum += __shfl_xor_sync(0xffffffffu, sum, 1, 16);
            sum += __shfl_xor_sync(0xffffffffu, sum, 2, 16);
            sum += __shfl_xor_sync(0xffffffffu, sum, 4, 16);
            sum += __shfl_xor_sync(0xffffffffu, sum, 8, 16);
            l[i] = l[i] * alpha + sum;
            m[i] = mn;
            #pragma unroll
            for (int j = 0; j < 4; ++j) o[i][j] *= alpha;
            #pragma unroll
            for (int j = 0; j < 4; ++j) Ps[(ty * 4 + i) * 65 + tx * 4 + j] = s[i][j];
        }
        __syncthreads();

        // O += P V  (contract over the 64 keys of this chunk)
        #pragma unroll 4
        for (int kk = 0; kk < 64; ++kk) {
            float4 v4 = *reinterpret_cast<const float4*>(Vs + kk * 64 + tx * 4);
            #pragma unroll
            for (int i = 0; i < 4; ++i) {
                float pv = Ps[(ty * 4 + i) * 65 + kk];
                o[i][0] += pv * v4.x;
                o[i][1] += pv * v4.y;
                o[i][2] += pv * v4.z;
                o[i][3] += pv * v4.w;
            }
        }
    }

    // epilogue: normalize, transpose to NCHW, add residual
    #pragma unroll
    for (int i = 0; i < 4; ++i) {
        float inv = 1.f / l[i];
        int p = rb * 64 + ty * 4 + i;
        #pragma unroll
        for (int j = 0; j < 4; ++j) {
            int cv = tx * 4 + j;
            int gi = (b * 64 + cv) * NPIX + p;
            out[gi] = o[i][j] * inv + __ldg(A1C + gi);
        }
    }
}

// ---------------------------------------------------------------------------
extern "C" void kernel_launch(void* const* d_in, const int* in_sizes, int n_in,
                              void* d_out, int out_size) {
    const float* A1B = (const float*)d_in[0];
    const float* A1C = (const float*)d_in[1];
    const float* w1  = (const float*)d_in[2];
    const float* b1  = (const float*)d_in[3];
    const float* w2  = (const float*)d_in[4];
    const float* b2  = (const float*)d_in[5];
    const float* w3  = (const float*)d_in[6];
    const float* b3  = (const float*)d_in[7];
    float* out = (float*)d_out;

    // idempotent; first (uncaptured) correctness call makes these stick
    cudaFuncSetAttribute(conv_kernel, cudaFuncAttributeMaxDynamicSharedMemorySize, CONV_SMEM);
    cudaFuncSetAttribute(attn_kernel, cudaFuncAttributeMaxDynamicSharedMemorySize, ATTN_SMEM);

    pack_kernel<<<288, 256>>>(w1, b1, w2, b2, w3, b3);
    conv_kernel<<<dim3(HW, NB), 256, CONV_SMEM>>>(A1B, A1C);
    attn_kernel<<<dim3(NPIX / 64, NB), 256, ATTN_SMEM>>>(A1C, out);
}